// round 4
// baseline (speedup 1.0000x reference)
#include <cuda_runtime.h>
#include <cuda_bf16.h>

__device__ float g_x3[4*3*256*256];
__device__ float g_x6[4*3*256*256];
__device__ float g_x9[4*3*256*256];
__device__ float g_xg[4];

__device__ __forceinline__ int reflect256(int t) {
    t = (t < 0) ? -t : t;
    return (t >= 256) ? (510 - t) : t;
}

// exp(-t/P) as compile-time literals
template<int P>
__device__ __forceinline__ constexpr float ebias(int t) {
    return (t == 0) ? 1.0f
         : (t == 1) ? ((P == 2) ? 0.60653065971263342f : 0.71653131057378927f)
         : 0.51341711903259202f; // t==2 only occurs for P==3
}

// per-batch max of x (the reference softmax over a singleton axis == 1)
__global__ __launch_bounds__(256) void max_kernel(const float* __restrict__ X) {
    int b = blockIdx.x;
    const float* xb = X + b*3*65536;
    float m = -1e30f;
    for (int i = threadIdx.x; i < 3*65536; i += 256)
        m = fmaxf(m, xb[i]);
    __shared__ float sm[8];
    #pragma unroll
    for (int o = 16; o > 0; o >>= 1) m = fmaxf(m, __shfl_xor_sync(0xffffffffu, m, o));
    if ((threadIdx.x & 31) == 0) sm[threadIdx.x >> 5] = m;
    __syncthreads();
    if (threadIdx.x < 32) {
        float v = (threadIdx.x < 8) ? sm[threadIdx.x] : -1e30f;
        #pragma unroll
        for (int o = 4; o > 0; o >>= 1) v = fmaxf(v, __shfl_xor_sync(0xffffffffu, v, o));
        if (threadIdx.x == 0) g_xg[b] = v;
    }
}

// stage 1: p=1, nh=6, bias==1. one thread per window, neighborhood in regs.
__global__ __launch_bounds__(256) void attn1_kernel(
    const float* __restrict__ X, const float* __restrict__ W,
    const float* __restrict__ B, const float* __restrict__ HW)
{
    int n = blockIdx.x*256 + threadIdx.x;
    int j = n & 255, i = (n >> 8) & 255, b = n >> 16;

    float xn[9][3];
    #pragma unroll
    for (int k = 0; k < 9; k++) {
        int yy = reflect256(i + k/3 - 1);
        int xx = reflect256(j + k%3 - 1);
        const float* p = X + b*3*65536 + yy*256 + xx;
        #pragma unroll
        for (int c = 0; c < 3; c++) xn[k][c] = p[c*65536];
    }

    const float rs = 0.5773502691896258f; // 1/sqrt(3)
    float res[3] = {0.f, 0.f, 0.f};

    #pragma unroll 1
    for (int h = 0; h < 6; h++) {
        float hw = __ldg(HW + h);
        #pragma unroll
        for (int c = 0; c < 3; c++) {
            int mq = (h*3+0)*3 + c, mk = (h*3+1)*3 + c, mv = (h*3+2)*3 + c;
            float q = __ldg(B+mq) + __ldg(W+mq*3+0)*xn[4][0]
                                  + __ldg(W+mq*3+1)*xn[4][1]
                                  + __ldg(W+mq*3+2)*xn[4][2];
            q *= rs;
            float wk0=__ldg(W+mk*3+0), wk1=__ldg(W+mk*3+1), wk2=__ldg(W+mk*3+2), bk=__ldg(B+mk);
            float sc[9], mx = -1e30f;
            #pragma unroll
            for (int k = 0; k < 9; k++) {
                float kv = bk + wk0*xn[k][0] + wk1*xn[k][1] + wk2*xn[k][2];
                sc[k] = q * kv;
                mx = fmaxf(mx, sc[k]);
            }
            float sum = 0.f;
            #pragma unroll
            for (int k = 0; k < 9; k++) { sc[k] = __expf(sc[k] - mx); sum += sc[k]; }
            float wv0=__ldg(W+mv*3+0), wv1=__ldg(W+mv*3+1), wv2=__ldg(W+mv*3+2), bv=__ldg(B+mv);
            float o = 0.f;
            #pragma unroll
            for (int k = 0; k < 9; k++) {
                float vv = bv + wv0*xn[k][0] + wv1*xn[k][1] + wv2*xn[k][2];
                o += sc[k]*vv;
            }
            res[c] += hw * o / sum;
        }
    }
    #pragma unroll
    for (int c = 0; c < 3; c++)
        g_x3[(b*3+c)*65536 + i*256 + j] = res[c];
}

// stages 2/3: thread = (window, head, c_out); row-chunked; all smem rows padded
// to LW floats (16B multiple) so every shared access is LDS.128.
template<int P, int NH, int WPB>
__global__ __launch_bounds__(WPB*NH*3, 4) void attn_kernel(
    const float* __restrict__ W, const float* __restrict__ B, const float* __restrict__ HW)
{
    constexpr int PP = P*P, L = 3*PP, HC = NH*3, M = NH*3*L;
    constexpr int LW  = (P==2) ? 12 : 28;       // padded row length (mult of 4)
    constexpr int LW4 = LW/4;
    constexpr int NHW  = (P==2) ? 128 : 86;
    constexpr int NWIN = 4*NHW*NHW;
    constexpr int PADH = (P==2) ? 0 : 2;
    constexpr int PADL = P + PADH;
    constexpr int XSP  = 9*LW;                  // padded window stride
    constexpr float RS = (P==2) ? 0.2886751345948129f : 0.1924500897298753f; // 1/sqrt(L)

    __shared__ __align__(16) float sx[WPB*XSP];
    __shared__ __align__(16) float sw[M*LW];

    const float* Xg = (P==2) ? g_x3 : g_x6;
    float*       Og = (P==2) ? g_x6 : g_x9;

    const int tid = threadIdx.x;
    constexpr int NTH = WPB*HC;

    // weights into padded smem (pad = 0)
    for (int idx = tid; idx < M*LW; idx += NTH) {
        int m = idx / LW, lp = idx % LW;
        sw[idx] = (lp < L) ? W[m*L + lp] : 0.f;
    }

    const int n0 = blockIdx.x * WPB;
    for (int idx = tid; idx < WPB*XSP; idx += NTH) {
        int wl = idx / XSP, rem = idx % XSP;
        int n = n0 + wl;
        int k9 = rem / LW, lp = rem % LW;
        float v = 0.f;
        if (n < NWIN && lp < L) {
            int wj = n % NHW, wi = (n / NHW) % NHW, b = n / (NHW*NHW);
            int c = lp / PP, rr = (lp % PP) / P, ss = lp % P;
            int y  = reflect256((wi + k9/3)*P + rr - PADL);
            int x2 = reflect256((wj + k9%3)*P + ss - PADL);
            v = Xg[(b*3+c)*65536 + y*256 + x2];
        }
        sx[idx] = v;
    }
    __syncthreads();

    const int hc = tid % HC, wl = tid / HC;
    const int h = hc % NH, c = hc / NH;
    const int n = n0 + wl;
    const bool active = (n < NWIN);
    const int wj = n % NHW, wi = (n / NHW) % NHW, b = n / (NHW*NHW);
    const float* xw = sx + wl*XSP;

    const int mqb = ((h*3+0)*3 + c)*PP;
    const int mkb = ((h*3+1)*3 + c)*PP;
    const int mvb = ((h*3+2)*3 + c)*PP;

    float score[9];
    #pragma unroll
    for (int k = 0; k < 9; k++) score[k] = 0.f;

    float wreg[P*LW];

    // ---- k pass, one row of positions at a time ----
    #pragma unroll 1
    for (int ii = 0; ii < P; ii++) {
        const int rowq = mqb + ii*P;
        const int rowk = mkb + ii*P;

        // q for this row
        float qr[P];
        #pragma unroll
        for (int jj = 0; jj < P; jj++) qr[jj] = __ldg(B + rowq + jj);
        #pragma unroll
        for (int jj = 0; jj < P; jj++)
            #pragma unroll
            for (int l4 = 0; l4 < LW4; l4++)
                *(float4*)&wreg[jj*LW + l4*4] = *(const float4*)&sw[(rowq+jj)*LW + l4*4];
        #pragma unroll
        for (int l4 = 0; l4 < LW4; l4++) {
            float4 xv = *(const float4*)&xw[4*LW + l4*4];
            #pragma unroll
            for (int jj = 0; jj < P; jj++) {
                qr[jj] += xv.x * wreg[jj*LW + l4*4+0];
                qr[jj] += xv.y * wreg[jj*LW + l4*4+1];
                qr[jj] += xv.z * wreg[jj*LW + l4*4+2];
                qr[jj] += xv.w * wreg[jj*LW + l4*4+3];
            }
        }
        #pragma unroll
        for (int jj = 0; jj < P; jj++) qr[jj] *= RS;

        // eu[di] = exp(-u/P): u = P-1-ii (di=0), 0 (di=1), ii (di=2)  [ii runtime]
        float eu0, eu2;
        if (P == 2) {
            eu0 = (ii == 0) ? ebias<P>(1) : ebias<P>(0);
            eu2 = (ii == 0) ? ebias<P>(0) : ebias<P>(1);
        } else {
            eu0 = (ii == 0) ? ebias<P>(2) : ((ii == 1) ? ebias<P>(1) : ebias<P>(0));
            eu2 = (ii == 0) ? ebias<P>(0) : ((ii == 1) ? ebias<P>(1) : ebias<P>(2));
        }
        float qe[3][P];
        #pragma unroll
        for (int jj = 0; jj < P; jj++) {
            qe[0][jj] = qr[jj]*eu0; qe[1][jj] = qr[jj]; qe[2][jj] = qr[jj]*eu2;
        }

        // k weights for this row
        float bk[P];
        #pragma unroll
        for (int jj = 0; jj < P; jj++) bk[jj] = __ldg(B + rowk + jj);
        #pragma unroll
        for (int jj = 0; jj < P; jj++)
            #pragma unroll
            for (int l4 = 0; l4 < LW4; l4++)
                *(float4*)&wreg[jj*LW + l4*4] = *(const float4*)&sw[(rowk+jj)*LW + l4*4];

        #pragma unroll
        for (int k = 0; k < 9; k++) {
            const int di = k/3, dj = k%3;
            float acc[P];
            #pragma unroll
            for (int jj = 0; jj < P; jj++) acc[jj] = bk[jj];
            #pragma unroll
            for (int l4 = 0; l4 < LW4; l4++) {
                float4 xv = *(const float4*)&xw[k*LW + l4*4];
                #pragma unroll
                for (int jj = 0; jj < P; jj++) {
                    acc[jj] += xv.x * wreg[jj*LW + l4*4+0];
                    acc[jj] += xv.y * wreg[jj*LW + l4*4+1];
                    acc[jj] += xv.z * wreg[jj*LW + l4*4+2];
                    acc[jj] += xv.w * wreg[jj*LW + l4*4+3];
                }
            }
            #pragma unroll
            for (int jj = 0; jj < P; jj++) {
                const float ev = (dj==0) ? ebias<P>(P-1-jj) : ((dj==1) ? 1.f : ebias<P>(jj));
                score[k] += qe[di][jj] * (ev * acc[jj]);
            }
        }
    }

    // softmax over the 9 neighbors
    float mx = score[0];
    #pragma unroll
    for (int k = 1; k < 9; k++) mx = fmaxf(mx, score[k]);
    float sum = 0.f;
    #pragma unroll
    for (int k = 0; k < 9; k++) { score[k] = __expf(score[k]-mx); sum += score[k]; }
    const float hwv = __ldg(HW + h) / sum;

    // ---- v pass, row at a time; reduce + store per row ----
    #pragma unroll 1
    for (int ii = 0; ii < P; ii++) {
        const int rowv = mvb + ii*P;
        float bv[P];
        #pragma unroll
        for (int jj = 0; jj < P; jj++) bv[jj] = __ldg(B + rowv + jj);
        #pragma unroll
        for (int jj = 0; jj < P; jj++)
            #pragma unroll
            for (int l4 = 0; l4 < LW4; l4++)
                *(float4*)&wreg[jj*LW + l4*4] = *(const float4*)&sw[(rowv+jj)*LW + l4*4];

        float outr[P];
        #pragma unroll
        for (int jj = 0; jj < P; jj++) outr[jj] = 0.f;
        #pragma unroll
        for (int k = 0; k < 9; k++) {
            float acc[P];
            #pragma unroll
            for (int jj = 0; jj < P; jj++) acc[jj] = bv[jj];
            #pragma unroll
            for (int l4 = 0; l4 < LW4; l4++) {
                float4 xv = *(const float4*)&xw[k*LW + l4*4];
                #pragma unroll
                for (int jj = 0; jj < P; jj++) {
                    acc[jj] += xv.x * wreg[jj*LW + l4*4+0];
                    acc[jj] += xv.y * wreg[jj*LW + l4*4+1];
                    acc[jj] += xv.z * wreg[jj*LW + l4*4+2];
                    acc[jj] += xv.w * wreg[jj*LW + l4*4+3];
                }
            }
            #pragma unroll
            for (int jj = 0; jj < P; jj++) outr[jj] += score[k] * acc[jj];
        }
        #pragma unroll
        for (int jj = 0; jj < P; jj++) outr[jj] *= hwv;

        // head reduction: NH adjacent lanes, aligned groups
        #pragma unroll
        for (int jj = 0; jj < P; jj++) {
            outr[jj] += __shfl_xor_sync(0xffffffffu, outr[jj], 1);
            if (NH == 4) outr[jj] += __shfl_xor_sync(0xffffffffu, outr[jj], 2);
        }

        if (h == 0 && active) {
            const int y = wi*P + ii - PADH;
            if (y >= 0) {
                #pragma unroll
                for (int jj = 0; jj < P; jj++) {
                    const int x2 = wj*P + jj - PADH;
                    if (x2 >= 0)
                        Og[(b*3+c)*65536 + y*256 + x2] = outr[jj];
                }
            }
        }
    }
}

// 5x5 conv (9->3 channels) fused with the final elementwise gate
__global__ __launch_bounds__(128) void conv_final_kernel(
    const float* __restrict__ X, const float* __restrict__ CW,
    const float* __restrict__ CB, float* __restrict__ out)
{
    __shared__ float sx[9][20][37];
    __shared__ float sw[675];
    __shared__ float sb[3];
    const int b = blockIdx.z;
    const int x0 = blockIdx.x * 32, y0 = blockIdx.y * 16;
    const int tid = threadIdx.x;

    for (int i2 = tid; i2 < 675; i2 += 128) sw[i2] = CW[i2];
    if (tid < 3) sb[tid] = CB[tid];
    for (int i2 = tid; i2 < 9*20*36; i2 += 128) {
        int ci = i2 / 720, rem = i2 % 720, yy = rem / 36, xx = rem % 36;
        int gy = y0 + yy - 2, gx = x0 + xx - 2;
        float v = 0.f;
        if ((unsigned)gy < 256u && (unsigned)gx < 256u) {
            const float* src = (ci < 3) ? g_x9 : ((ci < 6) ? g_x6 : g_x3);
            v = src[(b*3 + (ci % 3))*65536 + gy*256 + gx];
        }
        sx[ci][yy][xx] = v;
    }
    __syncthreads();

    const int tx = tid & 15, ty = tid >> 4;
    const int lx = tx*2, ly = ty*2;
    float acc[3][4];
    #pragma unroll
    for (int c2 = 0; c2 < 3; c2++)
        #pragma unroll
        for (int p2 = 0; p2 < 4; p2++) acc[c2][p2] = 0.f;

    #pragma unroll 1
    for (int ci = 0; ci < 9; ci++) {
        #pragma unroll
        for (int ky = 0; ky < 5; ky++) {
            #pragma unroll
            for (int kx = 0; kx < 5; kx++) {
                float w0 = sw[      ci*25 + ky*5 + kx];
                float w1 = sw[225 + ci*25 + ky*5 + kx];
                float w2 = sw[450 + ci*25 + ky*5 + kx];
                float a00 = sx[ci][ly+ky  ][lx+kx  ];
                float a01 = sx[ci][ly+ky  ][lx+kx+1];
                float a10 = sx[ci][ly+ky+1][lx+kx  ];
                float a11 = sx[ci][ly+ky+1][lx+kx+1];
                acc[0][0] += w0*a00; acc[0][1] += w0*a01; acc[0][2] += w0*a10; acc[0][3] += w0*a11;
                acc[1][0] += w1*a00; acc[1][1] += w1*a01; acc[1][2] += w1*a10; acc[1][3] += w1*a11;
                acc[2][0] += w2*a00; acc[2][1] += w2*a01; acc[2][2] += w2*a10; acc[2][3] += w2*a11;
            }
        }
    }

    const float xg = g_xg[b];
    #pragma unroll
    for (int co = 0; co < 3; co++) {
        #pragma unroll
        for (int py = 0; py < 2; py++) {
            #pragma unroll
            for (int px = 0; px < 2; px++) {
                int gy = y0 + ly + py, gx = x0 + lx + px;
                float x0v = fmaxf(acc[co][py*2+px] + sb[co], 0.f);
                float xv = X[(b*3+co)*65536 + gy*256 + gx];
                float r = fmaxf(xv * x0v + xg - x0v, 0.f);
                out[(b*3+co)*65536 + gy*256 + gx] = r;
            }
        }
    }
}

extern "C" void kernel_launch(void* const* d_in, const int* in_sizes, int n_in,
                              void* d_out, int out_size) {
    (void)in_sizes; (void)n_in; (void)out_size;
    const float* x   = (const float*)d_in[0];
    const float* w3  = (const float*)d_in[1];
    const float* b3  = (const float*)d_in[2];
    const float* hw3 = (const float*)d_in[3];
    const float* w6  = (const float*)d_in[4];
    const float* b6  = (const float*)d_in[5];
    const float* hw6 = (const float*)d_in[6];
    const float* w9  = (const float*)d_in[7];
    const float* b9  = (const float*)d_in[8];
    const float* hw9 = (const float*)d_in[9];
    const float* cw  = (const float*)d_in[10];
    const float* cb  = (const float*)d_in[11];
    float* out = (float*)d_out;

    max_kernel<<<4, 256>>>(x);
    attn1_kernel<<<1024, 256>>>(x, w3, b3, hw3);

    // stage 2: P=2, NH=4, WPB=16 -> 192 threads, 65536 windows
    attn_kernel<2, 4, 16><<<(65536 + 15) / 16, 16 * 12>>>(w6, b6, hw6);

    // stage 3: P=3, NH=2, WPB=16 -> 96 threads, 29584 windows
    attn_kernel<3, 2, 16><<<(29584 + 15) / 16, 16 * 6>>>(w9, b9, hw9);

    conv_final_kernel<<<dim3(8, 16, 4), 128>>>(x, cw, cb, out);
}

// round 5
// speedup vs baseline: 1.2238x; 1.2238x over previous
#include <cuda_runtime.h>
#include <cuda_bf16.h>

__device__ float g_x3[4*3*256*256];
__device__ float g_x6[4*3*256*256];
__device__ float g_x9[4*3*256*256];
__device__ float g_xg[4];
// qkv scratch: P=2: 4*130*130 tiles * 12 hc * 12 floats; P=3: 4*88*88 * 6 * 36
__device__ float g_scr2[4*130*130*144];
__device__ float g_scr3[4*88*88*216];

__device__ __forceinline__ int reflect256(int t) {
    t = (t < 0) ? -t : t;
    return (t >= 256) ? (510 - t) : t;
}

// exp(-t/P) as compile-time literals
template<int P>
__device__ __forceinline__ constexpr float ebias(int t) {
    return (t == 0) ? 1.0f
         : (t == 1) ? ((P == 2) ? 0.60653065971263342f : 0.71653131057378927f)
         : 0.51341711903259202f; // t==2 only for P==3
}

// per-batch max of x (reference softmax over singleton axis == 1)
__global__ __launch_bounds__(256) void max_kernel(const float* __restrict__ X) {
    int b = blockIdx.x;
    const float* xb = X + b*3*65536;
    float m = -1e30f;
    for (int i = threadIdx.x; i < 3*65536; i += 256)
        m = fmaxf(m, xb[i]);
    __shared__ float sm[8];
    #pragma unroll
    for (int o = 16; o > 0; o >>= 1) m = fmaxf(m, __shfl_xor_sync(0xffffffffu, m, o));
    if ((threadIdx.x & 31) == 0) sm[threadIdx.x >> 5] = m;
    __syncthreads();
    if (threadIdx.x < 32) {
        float v = (threadIdx.x < 8) ? sm[threadIdx.x] : -1e30f;
        #pragma unroll
        for (int o = 4; o > 0; o >>= 1) v = fmaxf(v, __shfl_xor_sync(0xffffffffu, v, o));
        if (threadIdx.x == 0) g_xg[b] = v;
    }
}

// stage 1: p=1, nh=6, bias==1. thread = (pixel, head); 32-pixel row block.
__global__ __launch_bounds__(192) void attn1_kernel(
    const float* __restrict__ X, const float* __restrict__ W,
    const float* __restrict__ B, const float* __restrict__ HW)
{
    __shared__ float sxr[3][3][34];   // [c][row][col]
    __shared__ float sred[6][96];

    const int bx = blockIdx.x;
    const int b  = bx >> 11;          // 2048 blocks per batch
    const int i  = (bx >> 3) & 255;
    const int j0 = (bx & 7) * 32;
    const int tid = threadIdx.x;

    for (int idx = tid; idx < 306; idx += 192) {
        int c = idx / 102, r2 = idx % 102, rr = r2 / 34, cc = r2 % 34;
        int y = reflect256(i + rr - 1), x2 = reflect256(j0 + cc - 1);
        sxr[c][rr][cc] = X[(b*3+c)*65536 + y*256 + x2];
    }
    __syncthreads();

    const int px = tid & 31, h = tid >> 5;

    float xn[9][3];
    #pragma unroll
    for (int k = 0; k < 9; k++)
        #pragma unroll
        for (int c = 0; c < 3; c++)
            xn[k][c] = sxr[c][k/3][px + k%3];

    const float rs = 0.5773502691896258f; // 1/sqrt(3)
    const float hw = __ldg(HW + h);

    #pragma unroll
    for (int c = 0; c < 3; c++) {
        int mq = (h*3+0)*3 + c, mk = (h*3+1)*3 + c, mv = (h*3+2)*3 + c;
        float q = __ldg(B+mq) + __ldg(W+mq*3+0)*xn[4][0]
                              + __ldg(W+mq*3+1)*xn[4][1]
                              + __ldg(W+mq*3+2)*xn[4][2];
        q *= rs;
        float wk0=__ldg(W+mk*3+0), wk1=__ldg(W+mk*3+1), wk2=__ldg(W+mk*3+2), bk=__ldg(B+mk);
        float sc[9], mx = -1e30f;
        #pragma unroll
        for (int k = 0; k < 9; k++) {
            float kv = bk + wk0*xn[k][0] + wk1*xn[k][1] + wk2*xn[k][2];
            sc[k] = q * kv;
            mx = fmaxf(mx, sc[k]);
        }
        float sum = 0.f;
        #pragma unroll
        for (int k = 0; k < 9; k++) { sc[k] = __expf(sc[k] - mx); sum += sc[k]; }
        float wv0=__ldg(W+mv*3+0), wv1=__ldg(W+mv*3+1), wv2=__ldg(W+mv*3+2), bv=__ldg(B+mv);
        float o = 0.f;
        #pragma unroll
        for (int k = 0; k < 9; k++) {
            float vv = bv + wv0*xn[k][0] + wv1*xn[k][1] + wv2*xn[k][2];
            o += sc[k]*vv;
        }
        sred[h][px*3 + c] = hw * o / sum;
    }
    __syncthreads();

    if (tid < 96) {
        float s = 0.f;
        #pragma unroll
        for (int hh = 0; hh < 6; hh++) s += sred[hh][tid];
        int pxx = tid / 3, c = tid % 3;
        g_x3[(b*3+c)*65536 + i*256 + j0 + pxx] = s;
    }
}

// ---- stages 2/3: projection kernel. thread = (tile, hc). ----
// scratch per tile per hc: [q SEC][k SEC][v SEC], q pre-scaled by 1/sqrt(L).
template<int P, int NH, int TPB>
__global__ __launch_bounds__(TPB*NH*3) void proj_kernel(
    const float* __restrict__ W, const float* __restrict__ B)
{
    constexpr int PP = P*P, L = 3*PP, HC = NH*3;
    constexpr int NT   = (P==2) ? 130 : 88;
    constexpr int PADL = (P==2) ? 2 : 5;
    constexpr int LW   = (P==2) ? 12 : 28;   // padded weight/x row
    constexpr int SEC  = (P==2) ? 4 : 12;    // padded section length
    constexpr int HSTR = 3*SEC, TSTR = HC*HSTR;
    constexpr int MROW = NH*9*PP;            // weight rows
    constexpr int NTILES = 4*NT*NT;
    constexpr int NTH = TPB*HC;
    constexpr float RS = (P==2) ? 0.2886751345948129f : 0.1924500897298753f;

    __shared__ __align__(16) float swt[MROW*LW];
    __shared__ __align__(16) float sxt[TPB*LW];

    const float* Xg = (P==2) ? g_x3 : g_x6;
    float* scr      = (P==2) ? g_scr2 : g_scr3;

    const int tid = threadIdx.x;
    for (int idx = tid; idx < MROW*LW; idx += NTH) {
        int m = idx / LW, lp = idx % LW;
        swt[idx] = (lp < L) ? W[m*L + lp] : 0.f;
    }
    const int t0 = blockIdx.x * TPB;
    for (int idx = tid; idx < TPB*LW; idx += NTH) {
        int tl = idx / LW, lp = idx % LW;
        int t = t0 + tl;
        float v = 0.f;
        if (t < NTILES && lp < L) {
            int tj = t % NT, ti = (t / NT) % NT, b = t / (NT*NT);
            int c = lp / PP, rr = (lp % PP) / P, ss = lp % P;
            int y  = reflect256(ti*P + rr - PADL);
            int x2 = reflect256(tj*P + ss - PADL);
            v = Xg[(b*3+c)*65536 + y*256 + x2];
        }
        sxt[idx] = v;
    }
    __syncthreads();

    const int hc = tid % HC, tl = tid / HC;
    const int t = t0 + tl;
    if (t >= NTILES) return;
    const int h = hc % NH, c = hc / NH;

    float xr[LW];
    #pragma unroll
    for (int l4 = 0; l4 < LW/4; l4++)
        *(float4*)&xr[l4*4] = *(const float4*)&sxt[tl*LW + l4*4];

    float* outb = scr + (size_t)t*TSTR + hc*HSTR;

    #pragma unroll
    for (int sec = 0; sec < 3; sec++) {
        const int row0 = ((h*3 + sec)*3 + c)*PP;
        float acc[SEC];
        #pragma unroll
        for (int pos = 0; pos < SEC; pos++) acc[pos] = 0.f;
        #pragma unroll
        for (int pos = 0; pos < PP; pos++) {
            float a = __ldg(B + row0 + pos);
            #pragma unroll
            for (int l4 = 0; l4 < LW/4; l4++) {
                float4 w4 = *(const float4*)&swt[(row0+pos)*LW + l4*4];
                a += w4.x*xr[l4*4+0] + w4.y*xr[l4*4+1]
                   + w4.z*xr[l4*4+2] + w4.w*xr[l4*4+3];
            }
            acc[pos] = (sec == 0) ? a*RS : a;
        }
        #pragma unroll
        for (int s4 = 0; s4 < SEC/4; s4++) {
            float4 o4;
            o4.x = acc[s4*4+0]; o4.y = acc[s4*4+1];
            o4.z = acc[s4*4+2]; o4.w = acc[s4*4+3];
            *(float4*)&outb[sec*SEC + s4*4] = o4;
        }
    }
}

// ---- stages 2/3: attention kernel. block = 4x4 window patch, thread = (window, hc). ----
template<int P, int NH>
__global__ __launch_bounds__(16*NH*3) void attn_win_kernel(const float* __restrict__ HW)
{
    constexpr int PP = P*P, HC = NH*3;
    constexpr int NT   = (P==2) ? 130 : 88;
    constexpr int NHW  = (P==2) ? 128 : 86;
    constexpr int PADH = (P==2) ? 0 : 2;
    constexpr int SEC  = (P==2) ? 4 : 12;
    constexpr int HSTR = 3*SEC, TSTR = HC*HSTR;
    constexpr int NTH = 16*HC;

    __shared__ __align__(16) float st[36*TSTR];

    const float* scr = (P==2) ? g_scr2 : g_scr3;
    float* Og        = (P==2) ? g_x6 : g_x9;

    const int tid = threadIdx.x;
    const int wi0 = blockIdx.y * 4, wj0 = blockIdx.x * 4;
    const int b = blockIdx.z;

    // cooperative load of 6x6 tile qkv block (float4 granularity)
    for (int f4 = tid; f4 < 36*(TSTR/4); f4 += NTH) {
        int tile_l = f4 / (TSTR/4), rem = f4 % (TSTR/4);
        int u = tile_l / 6, v = tile_l % 6;
        int ti = wi0 + u, tj = wj0 + v;
        float4 val = make_float4(0.f, 0.f, 0.f, 0.f);
        if (ti < NT && tj < NT)
            val = *(const float4*)&scr[(size_t)((b*NT + ti)*NT + tj)*TSTR + rem*4];
        *(float4*)&st[tile_l*TSTR + rem*4] = val;
    }
    __syncthreads();

    const int hc = tid % HC, wl = tid / HC;
    const int h = hc % NH;
    const int c = hc / NH;
    const int wl4 = wl >> 2, wlm = wl & 3;
    const int wi = wi0 + wl4, wj = wj0 + wlm;
    const bool active = (wi < NHW) && (wj < NHW);

    // q of core tile (pre-scaled)
    const float* core = st + ((wl4+1)*6 + (wlm+1))*TSTR + hc*HSTR;
    float q[SEC];
    #pragma unroll
    for (int s4 = 0; s4 < SEC/4; s4++)
        *(float4*)&q[s4*4] = *(const float4*)&core[s4*4];

    // qe[di][pos] = q[pos] * exp(-u/P), u = f(di, ii)
    float qe[3][PP];
    #pragma unroll
    for (int pos = 0; pos < PP; pos++) {
        const int ii = pos / P;
        qe[0][pos] = q[pos] * ebias<P>(P-1-ii);
        qe[1][pos] = q[pos];
        qe[2][pos] = q[pos] * ebias<P>(ii);
    }

    float score[9];
    #pragma unroll
    for (int k9 = 0; k9 < 9; k9++) {
        const int di = k9/3, dj = k9%3;
        const float* kt = st + ((wl4+di)*6 + (wlm+dj))*TSTR + hc*HSTR + SEC;
        float kv[SEC];
        #pragma unroll
        for (int s4 = 0; s4 < SEC/4; s4++)
            *(float4*)&kv[s4*4] = *(const float4*)&kt[s4*4];
        float s = 0.f;
        #pragma unroll
        for (int pos = 0; pos < PP; pos++) {
            const int jj = pos % P;
            const float ev = (dj==0) ? ebias<P>(P-1-jj) : ((dj==1) ? 1.f : ebias<P>(jj));
            s += qe[di][pos] * (ev * kv[pos]);
        }
        score[k9] = s;
    }

    float mx = score[0];
    #pragma unroll
    for (int k = 1; k < 9; k++) mx = fmaxf(mx, score[k]);
    float sum = 0.f;
    #pragma unroll
    for (int k = 0; k < 9; k++) { score[k] = __expf(score[k]-mx); sum += score[k]; }
    const float hwv = __ldg(HW + h) / sum;

    float outp[PP];
    #pragma unroll
    for (int pos = 0; pos < PP; pos++) outp[pos] = 0.f;
    #pragma unroll
    for (int k9 = 0; k9 < 9; k9++) {
        const float* vt = st + ((wl4 + k9/3)*6 + (wlm + k9%3))*TSTR + hc*HSTR + 2*SEC;
        float vv[SEC];
        #pragma unroll
        for (int s4 = 0; s4 < SEC/4; s4++)
            *(float4*)&vv[s4*4] = *(const float4*)&vt[s4*4];
        #pragma unroll
        for (int pos = 0; pos < PP; pos++) outp[pos] += score[k9] * vv[pos];
    }
    #pragma unroll
    for (int pos = 0; pos < PP; pos++) outp[pos] *= hwv;

    // head reduction over NH adjacent lanes (aligned groups)
    #pragma unroll
    for (int pos = 0; pos < PP; pos++) {
        outp[pos] += __shfl_xor_sync(0xffffffffu, outp[pos], 1);
        if (NH == 4) outp[pos] += __shfl_xor_sync(0xffffffffu, outp[pos], 2);
    }

    if (h == 0 && active) {
        #pragma unroll
        for (int pos = 0; pos < PP; pos++) {
            const int y  = wi*P + pos/P - PADH;
            const int x2 = wj*P + pos%P - PADH;
            if (y >= 0 && x2 >= 0)
                Og[(b*3+c)*65536 + y*256 + x2] = outp[pos];
        }
    }
}

// 5x5 conv (9->3 channels) fused with the final elementwise gate
__global__ __launch_bounds__(128) void conv_final_kernel(
    const float* __restrict__ X, const float* __restrict__ CW,
    const float* __restrict__ CB, float* __restrict__ out)
{
    __shared__ float sx[9][20][37];
    __shared__ float sw[675];
    __shared__ float sb[3];
    const int b = blockIdx.z;
    const int x0 = blockIdx.x * 32, y0 = blockIdx.y * 16;
    const int tid = threadIdx.x;

    for (int i2 = tid; i2 < 675; i2 += 128) sw[i2] = CW[i2];
    if (tid < 3) sb[tid] = CB[tid];
    for (int i2 = tid; i2 < 9*20*36; i2 += 128) {
        int ci = i2 / 720, rem = i2 % 720, yy = rem / 36, xx = rem % 36;
        int gy = y0 + yy - 2, gx = x0 + xx - 2;
        float v = 0.f;
        if ((unsigned)gy < 256u && (unsigned)gx < 256u) {
            const float* src = (ci < 3) ? g_x9 : ((ci < 6) ? g_x6 : g_x3);
            v = src[(b*3 + (ci % 3))*65536 + gy*256 + gx];
        }
        sx[ci][yy][xx] = v;
    }
    __syncthreads();

    const int tx = tid & 15, ty = tid >> 4;
    const int lx = tx*2, ly = ty*2;
    float acc[3][4];
    #pragma unroll
    for (int c2 = 0; c2 < 3; c2++)
        #pragma unroll
        for (int p2 = 0; p2 < 4; p2++) acc[c2][p2] = 0.f;

    #pragma unroll 1
    for (int ci = 0; ci < 9; ci++) {
        #pragma unroll
        for (int ky = 0; ky < 5; ky++) {
            #pragma unroll
            for (int kx = 0; kx < 5; kx++) {
                float w0 = sw[      ci*25 + ky*5 + kx];
                float w1 = sw[225 + ci*25 + ky*5 + kx];
                float w2 = sw[450 + ci*25 + ky*5 + kx];
                float a00 = sx[ci][ly+ky  ][lx+kx  ];
                float a01 = sx[ci][ly+ky  ][lx+kx+1];
                float a10 = sx[ci][ly+ky+1][lx+kx  ];
                float a11 = sx[ci][ly+ky+1][lx+kx+1];
                acc[0][0] += w0*a00; acc[0][1] += w0*a01; acc[0][2] += w0*a10; acc[0][3] += w0*a11;
                acc[1][0] += w1*a00; acc[1][1] += w1*a01; acc[1][2] += w1*a10; acc[1][3] += w1*a11;
                acc[2][0] += w2*a00; acc[2][1] += w2*a01; acc[2][2] += w2*a10; acc[2][3] += w2*a11;
            }
        }
    }

    const float xg = g_xg[b];
    #pragma unroll
    for (int co = 0; co < 3; co++) {
        #pragma unroll
        for (int py = 0; py < 2; py++) {
            #pragma unroll
            for (int px = 0; px < 2; px++) {
                int gy = y0 + ly + py, gx = x0 + lx + px;
                float x0v = fmaxf(acc[co][py*2+px] + sb[co], 0.f);
                float xv = X[(b*3+co)*65536 + gy*256 + gx];
                float r = fmaxf(xv * x0v + xg - x0v, 0.f);
                out[(b*3+co)*65536 + gy*256 + gx] = r;
            }
        }
    }
}

extern "C" void kernel_launch(void* const* d_in, const int* in_sizes, int n_in,
                              void* d_out, int out_size) {
    (void)in_sizes; (void)n_in; (void)out_size;
    const float* x   = (const float*)d_in[0];
    const float* w3  = (const float*)d_in[1];
    const float* b3  = (const float*)d_in[2];
    const float* hw3 = (const float*)d_in[3];
    const float* w6  = (const float*)d_in[4];
    const float* b6  = (const float*)d_in[5];
    const float* hw6 = (const float*)d_in[6];
    const float* w9  = (const float*)d_in[7];
    const float* b9  = (const float*)d_in[8];
    const float* hw9 = (const float*)d_in[9];
    const float* cw  = (const float*)d_in[10];
    const float* cb  = (const float*)d_in[11];
    float* out = (float*)d_out;

    max_kernel<<<4, 256>>>(x);
    attn1_kernel<<<8192, 192>>>(x, w3, b3, hw3);

    // stage 2: P=2, NH=4. tiles: 4*130*130 = 67600 (exact multiple of 16)
    proj_kernel<2, 4, 16><<<67600/16, 16*12>>>(w6, b6);
    attn_win_kernel<2, 4><<<dim3(32, 32, 4), 16*12>>>(hw6);

    // stage 3: P=3, NH=2. tiles: 4*88*88 = 30976 (exact multiple of 16)
    proj_kernel<3, 2, 16><<<30976/16, 16*6>>>(w9, b9);
    attn_win_kernel<3, 2><<<dim3(22, 22, 4), 16*6>>>(hw9);

    conv_final_kernel<<<dim3(8, 16, 4), 128>>>(x, cw, cb, out);
}

// round 6
// speedup vs baseline: 1.2797x; 1.0457x over previous
#include <cuda_runtime.h>
#include <cuda_bf16.h>

__device__ float g_x3[4*3*256*256];
__device__ float g_x6[4*3*256*256];
__device__ float g_x9[4*3*256*256];
__device__ float g_xg[4];
// qkv scratch: P=2: 4*130*130 tiles * 12 hc * 12 floats; P=3: 4*88*88 * 6 * 36
__device__ float g_scr2[4*130*130*144];
__device__ float g_scr3[4*88*88*216];

__device__ __forceinline__ int reflect256(int t) {
    t = (t < 0) ? -t : t;
    return (t >= 256) ? (510 - t) : t;
}

__device__ __forceinline__ float ex2(float x) {
    float y; asm("ex2.approx.f32 %0, %1;" : "=f"(y) : "f"(x)); return y;
}

#define LOG2E 1.4426950408889634f

// exp(-t/P) as compile-time literals
template<int P>
__device__ __forceinline__ constexpr float ebias(int t) {
    return (t == 0) ? 1.0f
         : (t == 1) ? ((P == 2) ? 0.60653065971263342f : 0.71653131057378927f)
         : 0.51341711903259202f; // t==2 only for P==3
}

// stage 1: p=1, nh=6, bias==1. thread = (pixel, head); 32-pixel row block.
// also folds the per-batch max of x (g_xg) via atomicMax on float-as-int (x >= 0).
__global__ __launch_bounds__(192) void attn1_kernel(
    const float* __restrict__ X, const float* __restrict__ W,
    const float* __restrict__ B, const float* __restrict__ HW)
{
    __shared__ float sxr[3][3][34];   // [c][row][col]
    __shared__ float sred[6][96];
    __shared__ float smax[6];

    const int bx = blockIdx.x;
    const int b  = bx >> 11;          // 2048 blocks per batch
    const int i  = (bx >> 3) & 255;
    const int j0 = (bx & 7) * 32;
    const int tid = threadIdx.x;

    float lm = 0.f;
    for (int idx = tid; idx < 306; idx += 192) {
        int c = idx / 102, r2 = idx % 102, rr = r2 / 34, cc = r2 % 34;
        int y = reflect256(i + rr - 1), x2 = reflect256(j0 + cc - 1);
        float v = X[(b*3+c)*65536 + y*256 + x2];
        sxr[c][rr][cc] = v;
        lm = fmaxf(lm, v);
    }
    // block max -> atomic
    #pragma unroll
    for (int o = 16; o > 0; o >>= 1) lm = fmaxf(lm, __shfl_xor_sync(0xffffffffu, lm, o));
    if ((tid & 31) == 0) smax[tid >> 5] = lm;
    __syncthreads();
    if (tid == 0) {
        float v = fmaxf(fmaxf(fmaxf(smax[0], smax[1]), fmaxf(smax[2], smax[3])),
                        fmaxf(smax[4], smax[5]));
        atomicMax((int*)&g_xg[b], __float_as_int(v));
    }

    const int px = tid & 31, h = tid >> 5;

    float xn[9][3];
    #pragma unroll
    for (int k = 0; k < 9; k++)
        #pragma unroll
        for (int c = 0; c < 3; c++)
            xn[k][c] = sxr[c][k/3][px + k%3];

    const float rsl = 0.5773502691896258f * LOG2E; // (1/sqrt(3)) * log2(e)
    const float hw = __ldg(HW + h);

    #pragma unroll
    for (int c = 0; c < 3; c++) {
        int mq = (h*3+0)*3 + c, mk = (h*3+1)*3 + c, mv = (h*3+2)*3 + c;
        float q = __ldg(B+mq) + __ldg(W+mq*3+0)*xn[4][0]
                              + __ldg(W+mq*3+1)*xn[4][1]
                              + __ldg(W+mq*3+2)*xn[4][2];
        q *= rsl;
        float wk0=__ldg(W+mk*3+0), wk1=__ldg(W+mk*3+1), wk2=__ldg(W+mk*3+2), bk=__ldg(B+mk);
        float wv0=__ldg(W+mv*3+0), wv1=__ldg(W+mv*3+1), wv2=__ldg(W+mv*3+2), bv=__ldg(B+mv);
        float sum = 0.f, o = 0.f;
        #pragma unroll
        for (int k = 0; k < 9; k++) {
            float kv = bk + wk0*xn[k][0] + wk1*xn[k][1] + wk2*xn[k][2];
            float p = ex2(q * kv);          // exp(score), log2e folded into q
            sum += p;
            float vv = bv + wv0*xn[k][0] + wv1*xn[k][1] + wv2*xn[k][2];
            o += p * vv;
        }
        sred[h][px*3 + c] = hw * __fdividef(o, sum);
    }
    __syncthreads();

    if (tid < 96) {
        float s = 0.f;
        #pragma unroll
        for (int hh = 0; hh < 6; hh++) s += sred[hh][tid];
        int pxx = tid / 3, c = tid % 3;
        g_x3[(b*3+c)*65536 + i*256 + j0 + pxx] = s;
    }
}

// ---- stages 2/3: projection kernel. thread = (tile, hc). ----
// scratch per tile per hc: [q SEC][k SEC][v SEC], q pre-scaled by log2e/sqrt(L).
template<int P, int NH, int TPB>
__global__ __launch_bounds__(TPB*NH*3) void proj_kernel(
    const float* __restrict__ W, const float* __restrict__ B)
{
    constexpr int PP = P*P, L = 3*PP, HC = NH*3;
    constexpr int NT   = (P==2) ? 130 : 88;
    constexpr int PADL = (P==2) ? 2 : 5;
    constexpr int LW   = (P==2) ? 12 : 28;   // padded weight/x row
    constexpr int SEC  = (P==2) ? 4 : 12;    // padded section length
    constexpr int HSTR = 3*SEC, TSTR = HC*HSTR;
    constexpr int MROW = NH*9*PP;            // weight rows
    constexpr int NTILES = 4*NT*NT;
    constexpr int NTH = TPB*HC;
    constexpr float RS = ((P==2) ? 0.2886751345948129f : 0.1924500897298753f) * LOG2E;

    __shared__ __align__(16) float swt[MROW*LW];
    __shared__ __align__(16) float sxt[TPB*LW];

    const float* Xg = (P==2) ? g_x3 : g_x6;
    float* scr      = (P==2) ? g_scr2 : g_scr3;

    const int tid = threadIdx.x;
    for (int idx = tid; idx < MROW*LW; idx += NTH) {
        int m = idx / LW, lp = idx % LW;
        swt[idx] = (lp < L) ? W[m*L + lp] : 0.f;
    }
    const int t0 = blockIdx.x * TPB;
    for (int idx = tid; idx < TPB*LW; idx += NTH) {
        int tl = idx / LW, lp = idx % LW;
        int t = t0 + tl;
        float v = 0.f;
        if (t < NTILES && lp < L) {
            int tj = t % NT, ti = (t / NT) % NT, b = t / (NT*NT);
            int c = lp / PP, rr = (lp % PP) / P, ss = lp % P;
            int y  = reflect256(ti*P + rr - PADL);
            int x2 = reflect256(tj*P + ss - PADL);
            v = Xg[(b*3+c)*65536 + y*256 + x2];
        }
        sxt[idx] = v;
    }
    __syncthreads();

    const int hc = tid % HC, tl = tid / HC;
    const int t = t0 + tl;
    if (t >= NTILES) return;
    const int h = hc % NH, c = hc / NH;

    float xr[LW];
    #pragma unroll
    for (int l4 = 0; l4 < LW/4; l4++)
        *(float4*)&xr[l4*4] = *(const float4*)&sxt[tl*LW + l4*4];

    float* outb = scr + (size_t)t*TSTR + hc*HSTR;

    #pragma unroll
    for (int sec = 0; sec < 3; sec++) {
        const int row0 = ((h*3 + sec)*3 + c)*PP;
        float acc[SEC];
        #pragma unroll
        for (int pos = 0; pos < SEC; pos++) acc[pos] = 0.f;
        #pragma unroll
        for (int pos = 0; pos < PP; pos++) {
            float a = __ldg(B + row0 + pos);
            #pragma unroll
            for (int l4 = 0; l4 < LW/4; l4++) {
                float4 w4 = *(const float4*)&swt[(row0+pos)*LW + l4*4];
                a += w4.x*xr[l4*4+0] + w4.y*xr[l4*4+1]
                   + w4.z*xr[l4*4+2] + w4.w*xr[l4*4+3];
            }
            acc[pos] = (sec == 0) ? a*RS : a;
        }
        #pragma unroll
        for (int s4 = 0; s4 < SEC/4; s4++) {
            float4 o4;
            o4.x = acc[s4*4+0]; o4.y = acc[s4*4+1];
            o4.z = acc[s4*4+2]; o4.w = acc[s4*4+3];
            *(float4*)&outb[sec*SEC + s4*4] = o4;
        }
    }
}

// ---- stages 2/3: attention kernel. block = 4x4 window patch, thread = (window, hc). ----
template<int P, int NH>
__global__ __launch_bounds__(16*NH*3) void attn_win_kernel(const float* __restrict__ HW)
{
    constexpr int PP = P*P, HC = NH*3;
    constexpr int NT   = (P==2) ? 130 : 88;
    constexpr int NHW  = (P==2) ? 128 : 86;
    constexpr int PADH = (P==2) ? 0 : 2;
    constexpr int SEC  = (P==2) ? 4 : 12;
    constexpr int HSTR = 3*SEC, TSTR = HC*HSTR;
    constexpr int NTH = 16*HC;

    __shared__ __align__(16) float st[36*TSTR];

    const float* scr = (P==2) ? g_scr2 : g_scr3;
    float* Og        = (P==2) ? g_x6 : g_x9;

    const int tid = threadIdx.x;
    const int wi0 = blockIdx.y * 4, wj0 = blockIdx.x * 4;
    const int b = blockIdx.z;

    // cooperative load of 6x6 tile qkv block (float4 granularity)
    for (int f4 = tid; f4 < 36*(TSTR/4); f4 += NTH) {
        int tile_l = f4 / (TSTR/4), rem = f4 % (TSTR/4);
        int u = tile_l / 6, v = tile_l % 6;
        int ti = wi0 + u, tj = wj0 + v;
        float4 val = make_float4(0.f, 0.f, 0.f, 0.f);
        if (ti < NT && tj < NT)
            val = *(const float4*)&scr[(size_t)((b*NT + ti)*NT + tj)*TSTR + rem*4];
        *(float4*)&st[tile_l*TSTR + rem*4] = val;
    }
    __syncthreads();

    const int hc = tid % HC, wl = tid / HC;
    const int h = hc % NH;
    const int c = hc / NH;
    const int wl4 = wl >> 2, wlm = wl & 3;
    const int wi = wi0 + wl4, wj = wj0 + wlm;
    const bool active = (wi < NHW) && (wj < NHW);

    // q of core tile (pre-scaled by log2e/sqrt(L))
    const float* core = st + ((wl4+1)*6 + (wlm+1))*TSTR + hc*HSTR;
    float q[SEC];
    #pragma unroll
    for (int s4 = 0; s4 < SEC/4; s4++)
        *(float4*)&q[s4*4] = *(const float4*)&core[s4*4];

    // qe[di][pos] = q[pos] * exp(-u/P), u = f(di, ii)
    float qe[3][PP];
    #pragma unroll
    for (int pos = 0; pos < PP; pos++) {
        const int ii = pos / P;
        qe[0][pos] = q[pos] * ebias<P>(P-1-ii);
        qe[1][pos] = q[pos];
        qe[2][pos] = q[pos] * ebias<P>(ii);
    }

    float score[9];
    #pragma unroll
    for (int k9 = 0; k9 < 9; k9++) {
        const int di = k9/3, dj = k9%3;
        const float* kt = st + ((wl4+di)*6 + (wlm+dj))*TSTR + hc*HSTR + SEC;
        float kv[SEC];
        #pragma unroll
        for (int s4 = 0; s4 < SEC/4; s4++)
            *(float4*)&kv[s4*4] = *(const float4*)&kt[s4*4];
        float s = 0.f;
        #pragma unroll
        for (int pos = 0; pos < PP; pos++) {
            const int jj = pos % P;
            const float ev = (dj==0) ? ebias<P>(P-1-jj) : ((dj==1) ? 1.f : ebias<P>(jj));
            s += qe[di][pos] * (ev * kv[pos]);
        }
        score[k9] = ex2(s);   // exp(raw score), log2e pre-folded into q
    }

    float sum = 0.f;
    #pragma unroll
    for (int k = 0; k < 9; k++) sum += score[k];
    const float hwv = __fdividef(__ldg(HW + h), sum);

    float outp[PP];
    #pragma unroll
    for (int pos = 0; pos < PP; pos++) outp[pos] = 0.f;
    #pragma unroll
    for (int k9 = 0; k9 < 9; k9++) {
        const float* vt = st + ((wl4 + k9/3)*6 + (wlm + k9%3))*TSTR + hc*HSTR + 2*SEC;
        float vv[SEC];
        #pragma unroll
        for (int s4 = 0; s4 < SEC/4; s4++)
            *(float4*)&vv[s4*4] = *(const float4*)&vt[s4*4];
        #pragma unroll
        for (int pos = 0; pos < PP; pos++) outp[pos] += score[k9] * vv[pos];
    }
    #pragma unroll
    for (int pos = 0; pos < PP; pos++) outp[pos] *= hwv;

    // head reduction over NH adjacent lanes (aligned groups)
    #pragma unroll
    for (int pos = 0; pos < PP; pos++) {
        outp[pos] += __shfl_xor_sync(0xffffffffu, outp[pos], 1);
        if (NH == 4) outp[pos] += __shfl_xor_sync(0xffffffffu, outp[pos], 2);
    }

    if (h == 0 && active) {
        #pragma unroll
        for (int pos = 0; pos < PP; pos++) {
            const int y  = wi*P + pos/P - PADH;
            const int x2 = wj*P + pos%P - PADH;
            if (y >= 0 && x2 >= 0)
                Og[(b*3+c)*65536 + y*256 + x2] = outp[pos];
        }
    }
}

// 5x5 conv (9->3 channels) fused with the final elementwise gate
__global__ __launch_bounds__(128) void conv_final_kernel(
    const float* __restrict__ X, const float* __restrict__ CW,
    const float* __restrict__ CB, float* __restrict__ out)
{
    __shared__ float sx[9][20][37];
    __shared__ float sw[675];
    __shared__ float sb[3];
    const int b = blockIdx.z;
    const int x0 = blockIdx.x * 32, y0 = blockIdx.y * 16;
    const int tid = threadIdx.x;

    for (int i2 = tid; i2 < 675; i2 += 128) sw[i2] = CW[i2];
    if (tid < 3) sb[tid] = CB[tid];
    for (int i2 = tid; i2 < 9*20*36; i2 += 128) {
        int ci = i2 / 720, rem = i2 % 720, yy = rem / 36, xx = rem % 36;
        int gy = y0 + yy - 2, gx = x0 + xx - 2;
        float v = 0.f;
        if ((unsigned)gy < 256u && (unsigned)gx < 256u) {
            const float* src = (ci < 3) ? g_x9 : ((ci < 6) ? g_x6 : g_x3);
            v = src[(b*3 + (ci % 3))*65536 + gy*256 + gx];
        }
        sx[ci][yy][xx] = v;
    }
    __syncthreads();

    const int tx = tid & 15, ty = tid >> 4;
    const int lx = tx*2, ly = ty*2;
    float acc[3][4];
    #pragma unroll
    for (int c2 = 0; c2 < 3; c2++)
        #pragma unroll
        for (int p2 = 0; p2 < 4; p2++) acc[c2][p2] = 0.f;

    #pragma unroll 1
    for (int ci = 0; ci < 9; ci++) {
        #pragma unroll
        for (int ky = 0; ky < 5; ky++) {
            #pragma unroll
            for (int kx = 0; kx < 5; kx++) {
                float w0 = sw[      ci*25 + ky*5 + kx];
                float w1 = sw[225 + ci*25 + ky*5 + kx];
                float w2 = sw[450 + ci*25 + ky*5 + kx];
                float a00 = sx[ci][ly+ky  ][lx+kx  ];
                float a01 = sx[ci][ly+ky  ][lx+kx+1];
                float a10 = sx[ci][ly+ky+1][lx+kx  ];
                float a11 = sx[ci][ly+ky+1][lx+kx+1];
                acc[0][0] += w0*a00; acc[0][1] += w0*a01; acc[0][2] += w0*a10; acc[0][3] += w0*a11;
                acc[1][0] += w1*a00; acc[1][1] += w1*a01; acc[1][2] += w1*a10; acc[1][3] += w1*a11;
                acc[2][0] += w2*a00; acc[2][1] += w2*a01; acc[2][2] += w2*a10; acc[2][3] += w2*a11;
            }
        }
    }

    const float xg = g_xg[b];
    #pragma unroll
    for (int co = 0; co < 3; co++) {
        #pragma unroll
        for (int py = 0; py < 2; py++) {
            #pragma unroll
            for (int px = 0; px < 2; px++) {
                int gy = y0 + ly + py, gx = x0 + lx + px;
                float x0v = fmaxf(acc[co][py*2+px] + sb[co], 0.f);
                float xv = X[(b*3+co)*65536 + gy*256 + gx];
                float r = fmaxf(xv * x0v + xg - x0v, 0.f);
                out[(b*3+co)*65536 + gy*256 + gx] = r;
            }
        }
    }
}

extern "C" void kernel_launch(void* const* d_in, const int* in_sizes, int n_in,
                              void* d_out, int out_size) {
    (void)in_sizes; (void)n_in; (void)out_size;
    const float* x   = (const float*)d_in[0];
    const float* w3  = (const float*)d_in[1];
    const float* b3  = (const float*)d_in[2];
    const float* hw3 = (const float*)d_in[3];
    const float* w6  = (const float*)d_in[4];
    const float* b6  = (const float*)d_in[5];
    const float* hw6 = (const float*)d_in[6];
    const float* w9  = (const float*)d_in[7];
    const float* b9  = (const float*)d_in[8];
    const float* hw9 = (const float*)d_in[9];
    const float* cw  = (const float*)d_in[10];
    const float* cb  = (const float*)d_in[11];
    float* out = (float*)d_out;

    // reset g_xg (x >= 0 so zero-init is a valid identity for max)
    void* xg_ptr = nullptr;
    cudaGetSymbolAddress(&xg_ptr, g_xg);
    cudaMemsetAsync(xg_ptr, 0, 4*sizeof(float));

    attn1_kernel<<<8192, 192>>>(x, w3, b3, hw3);

    // stage 2: P=2, NH=4. tiles: 4*130*130 = 67600 (exact multiple of 16)
    proj_kernel<2, 4, 16><<<67600/16, 16*12>>>(w6, b6);
    attn_win_kernel<2, 4><<<dim3(32, 32, 4), 16*12>>>(hw6);

    // stage 3: P=3, NH=2. tiles: 4*88*88 = 30976 (exact multiple of 16)
    proj_kernel<3, 2, 16><<<30976/16, 16*6>>>(w9, b9);
    attn_win_kernel<3, 2><<<dim3(22, 22, 4), 16*6>>>(hw9);

    conv_final_kernel<<<dim3(8, 16, 4), 128>>>(x, cw, cb, out);
}

// round 7
// speedup vs baseline: 1.8791x; 1.4683x over previous
#include <cuda_runtime.h>
#include <cuda_bf16.h>

__device__ float g_x3[4*3*256*256];
__device__ float g_x6[4*3*256*256];
__device__ float g_x9[4*3*256*256];
__device__ float g_xg[4];
// qkv scratch: P=2: 4*130*130 tiles * 12 hc * 12 floats; P=3: 4*88*88 * 6 * 36
__device__ float g_scr2[4*130*130*144];
__device__ float g_scr3[4*88*88*216];

__device__ __forceinline__ int reflect256(int t) {
    t = (t < 0) ? -t : t;
    return (t >= 256) ? (510 - t) : t;
}

__device__ __forceinline__ float ex2(float x) {
    float y; asm("ex2.approx.f32 %0, %1;" : "=f"(y) : "f"(x)); return y;
}

#define LOG2E 1.4426950408889634f

// exp(-t/P) as compile-time literals
template<int P>
__device__ __forceinline__ constexpr float ebias(int t) {
    return (t == 0) ? 1.0f
         : (t == 1) ? ((P == 2) ? 0.60653065971263342f : 0.71653131057378927f)
         : 0.51341711903259202f; // t==2 only for P==3
}

// stage 1: p=1, nh=6, bias==1. thread = (pixel, head); 32-pixel row block.
// also folds the per-batch max of x (g_xg) via atomicMax on float-as-int (x >= 0).
__global__ __launch_bounds__(192) void attn1_kernel(
    const float* __restrict__ X, const float* __restrict__ W,
    const float* __restrict__ B, const float* __restrict__ HW)
{
    __shared__ float sxr[3][3][34];   // [c][row][col]
    __shared__ float sred[6][96];
    __shared__ float smax[6];

    const int bx = blockIdx.x;
    const int b  = bx >> 11;          // 2048 blocks per batch
    const int i  = (bx >> 3) & 255;
    const int j0 = (bx & 7) * 32;
    const int tid = threadIdx.x;

    float lm = 0.f;
    for (int idx = tid; idx < 306; idx += 192) {
        int c = idx / 102, r2 = idx % 102, rr = r2 / 34, cc = r2 % 34;
        int y = reflect256(i + rr - 1), x2 = reflect256(j0 + cc - 1);
        float v = X[(b*3+c)*65536 + y*256 + x2];
        sxr[c][rr][cc] = v;
        lm = fmaxf(lm, v);
    }
    // block max -> atomic
    #pragma unroll
    for (int o = 16; o > 0; o >>= 1) lm = fmaxf(lm, __shfl_xor_sync(0xffffffffu, lm, o));
    if ((tid & 31) == 0) smax[tid >> 5] = lm;
    __syncthreads();
    if (tid == 0) {
        float v = fmaxf(fmaxf(fmaxf(smax[0], smax[1]), fmaxf(smax[2], smax[3])),
                        fmaxf(smax[4], smax[5]));
        atomicMax((int*)&g_xg[b], __float_as_int(v));
    }

    const int px = tid & 31, h = tid >> 5;

    float xn[9][3];
    #pragma unroll
    for (int k = 0; k < 9; k++)
        #pragma unroll
        for (int c = 0; c < 3; c++)
            xn[k][c] = sxr[c][k/3][px + k%3];

    const float rsl = 0.5773502691896258f * LOG2E; // (1/sqrt(3)) * log2(e)
    const float hw = __ldg(HW + h);

    #pragma unroll
    for (int c = 0; c < 3; c++) {
        int mq = (h*3+0)*3 + c, mk = (h*3+1)*3 + c, mv = (h*3+2)*3 + c;
        float q = __ldg(B+mq) + __ldg(W+mq*3+0)*xn[4][0]
                              + __ldg(W+mq*3+1)*xn[4][1]
                              + __ldg(W+mq*3+2)*xn[4][2];
        q *= rsl;
        float wk0=__ldg(W+mk*3+0), wk1=__ldg(W+mk*3+1), wk2=__ldg(W+mk*3+2), bk=__ldg(B+mk);
        float wv0=__ldg(W+mv*3+0), wv1=__ldg(W+mv*3+1), wv2=__ldg(W+mv*3+2), bv=__ldg(B+mv);
        float sum = 0.f, o = 0.f;
        #pragma unroll
        for (int k = 0; k < 9; k++) {
            float kv = bk + wk0*xn[k][0] + wk1*xn[k][1] + wk2*xn[k][2];
            float p = ex2(q * kv);          // exp(score), log2e folded into q
            sum += p;
            float vv = bv + wv0*xn[k][0] + wv1*xn[k][1] + wv2*xn[k][2];
            o += p * vv;
        }
        sred[h][px*3 + c] = hw * __fdividef(o, sum);
    }
    __syncthreads();

    if (tid < 96) {
        float s = 0.f;
        #pragma unroll
        for (int hh = 0; hh < 6; hh++) s += sred[hh][tid];
        int pxx = tid / 3, c = tid % 3;
        g_x3[(b*3+c)*65536 + i*256 + j0 + pxx] = s;
    }
}

// ---- stages 2/3: projection. warp = hc (weight reads broadcast), lane = tile. ----
// scratch per tile per hc: [q SEC][k SEC][v SEC], q pre-scaled by log2e/sqrt(L).
template<int P, int NH>
__global__ __launch_bounds__(NH*3*32) void proj_kernel(
    const float* __restrict__ W, const float* __restrict__ B)
{
    constexpr int PP = P*P, L = 3*PP, HC = NH*3;
    constexpr int NT   = (P==2) ? 130 : 88;
    constexpr int PADL = (P==2) ? 2 : 5;
    constexpr int LW   = (P==2) ? 12 : 28;   // padded weight row (mult of 4)
    constexpr int SEC  = (P==2) ? 4 : 12;    // padded section length
    constexpr int HSTR = 3*SEC, TSTR = HC*HSTR;
    constexpr int MROW = NH*9*PP;            // total weight rows
    constexpr int NTILES = 4*NT*NT;
    constexpr int NTH = HC*32;
    constexpr float RS = ((P==2) ? 0.2886751345948129f : 0.1924500897298753f) * LOG2E;

    __shared__ __align__(16) float swt[MROW*LW];
    __shared__ float sxt[LW][32];            // transposed: [l][tile-lane]

    const float* Xg = (P==2) ? g_x3 : g_x6;
    float* scr      = (P==2) ? g_scr2 : g_scr3;

    const int tid = threadIdx.x;
    const int t0 = blockIdx.x * 32;

    // weights into padded smem (pad = 0)
    for (int idx = tid; idx < MROW*LW; idx += NTH) {
        int m = idx / LW, lp = idx % LW;
        swt[idx] = (lp < L) ? W[m*L + lp] : 0.f;
    }
    // x tile rows, transposed so lane reads are conflict-free
    for (int idx = tid; idx < LW*32; idx += NTH) {
        int lp = idx / 32, lane2 = idx % 32;
        int t = t0 + lane2;
        float v = 0.f;
        if (t < NTILES && lp < L) {
            int tj = t % NT, ti = (t / NT) % NT, b = t / (NT*NT);
            int c = lp / PP, rr = (lp % PP) / P, ss = lp % P;
            int y  = reflect256(ti*P + rr - PADL);
            int x2 = reflect256(tj*P + ss - PADL);
            v = Xg[(b*3+c)*65536 + y*256 + x2];
        }
        sxt[lp][lane2] = v;
    }
    __syncthreads();

    const int hc = tid >> 5, lane = tid & 31;
    const int h = hc % NH, c = hc / NH;
    const int t = t0 + lane;
    const bool active = (t < NTILES);

    float xr[LW];
    #pragma unroll
    for (int l = 0; l < LW; l++) xr[l] = sxt[l][lane];

    float* outb = scr + (size_t)t*TSTR + hc*HSTR;

    #pragma unroll
    for (int sec = 0; sec < 3; sec++) {
        const int row0 = ((h*3 + sec)*3 + c)*PP;
        float acc[SEC];
        #pragma unroll
        for (int pos = 0; pos < SEC; pos++) acc[pos] = 0.f;
        #pragma unroll
        for (int pos = 0; pos < PP; pos++) {
            float a = __ldg(B + row0 + pos);
            #pragma unroll
            for (int l4 = 0; l4 < LW/4; l4++) {
                float4 w4 = *(const float4*)&swt[(row0+pos)*LW + l4*4];  // broadcast
                a += w4.x*xr[l4*4+0] + w4.y*xr[l4*4+1]
                   + w4.z*xr[l4*4+2] + w4.w*xr[l4*4+3];
            }
            acc[pos] = (sec == 0) ? a*RS : a;
        }
        if (active) {
            #pragma unroll
            for (int s4 = 0; s4 < SEC/4; s4++) {
                float4 o4;
                o4.x = acc[s4*4+0]; o4.y = acc[s4*4+1];
                o4.z = acc[s4*4+2]; o4.w = acc[s4*4+3];
                *(float4*)&outb[sec*SEC + s4*4] = o4;
            }
        }
    }
}

// ---- stages 2/3: attention kernel. block = 4x4 window patch, thread = (window, hc). ----
template<int P, int NH>
__global__ __launch_bounds__(16*NH*3) void attn_win_kernel(const float* __restrict__ HW)
{
    constexpr int PP = P*P, HC = NH*3;
    constexpr int NT   = (P==2) ? 130 : 88;
    constexpr int NHW  = (P==2) ? 128 : 86;
    constexpr int PADH = (P==2) ? 0 : 2;
    constexpr int SEC  = (P==2) ? 4 : 12;
    constexpr int HSTR = 3*SEC, TSTR = HC*HSTR;
    constexpr int NTH = 16*HC;

    __shared__ __align__(16) float st[36*TSTR];

    const float* scr = (P==2) ? g_scr2 : g_scr3;
    float* Og        = (P==2) ? g_x6 : g_x9;

    const int tid = threadIdx.x;
    const int wi0 = blockIdx.y * 4, wj0 = blockIdx.x * 4;
    const int b = blockIdx.z;

    // cooperative load of 6x6 tile qkv block (float4 granularity)
    for (int f4 = tid; f4 < 36*(TSTR/4); f4 += NTH) {
        int tile_l = f4 / (TSTR/4), rem = f4 % (TSTR/4);
        int u = tile_l / 6, v = tile_l % 6;
        int ti = wi0 + u, tj = wj0 + v;
        float4 val = make_float4(0.f, 0.f, 0.f, 0.f);
        if (ti < NT && tj < NT)
            val = *(const float4*)&scr[(size_t)((b*NT + ti)*NT + tj)*TSTR + rem*4];
        *(float4*)&st[tile_l*TSTR + rem*4] = val;
    }
    __syncthreads();

    const int hc = tid % HC, wl = tid / HC;
    const int h = hc % NH;
    const int c = hc / NH;
    const int wl4 = wl >> 2, wlm = wl & 3;
    const int wi = wi0 + wl4, wj = wj0 + wlm;
    const bool active = (wi < NHW) && (wj < NHW);

    // q of core tile (pre-scaled by log2e/sqrt(L))
    const float* core = st + ((wl4+1)*6 + (wlm+1))*TSTR + hc*HSTR;
    float q[SEC];
    #pragma unroll
    for (int s4 = 0; s4 < SEC/4; s4++)
        *(float4*)&q[s4*4] = *(const float4*)&core[s4*4];

    // qe[di][pos] = q[pos] * exp(-u/P), u = f(di, ii)
    float qe[3][PP];
    #pragma unroll
    for (int pos = 0; pos < PP; pos++) {
        const int ii = pos / P;
        qe[0][pos] = q[pos] * ebias<P>(P-1-ii);
        qe[1][pos] = q[pos];
        qe[2][pos] = q[pos] * ebias<P>(ii);
    }

    float score[9];
    #pragma unroll
    for (int k9 = 0; k9 < 9; k9++) {
        const int di = k9/3, dj = k9%3;
        const float* kt = st + ((wl4+di)*6 + (wlm+dj))*TSTR + hc*HSTR + SEC;
        float kv[SEC];
        #pragma unroll
        for (int s4 = 0; s4 < SEC/4; s4++)
            *(float4*)&kv[s4*4] = *(const float4*)&kt[s4*4];
        float s = 0.f;
        #pragma unroll
        for (int pos = 0; pos < PP; pos++) {
            const int jj = pos % P;
            const float ev = (dj==0) ? ebias<P>(P-1-jj) : ((dj==1) ? 1.f : ebias<P>(jj));
            s += qe[di][pos] * (ev * kv[pos]);
        }
        score[k9] = ex2(s);   // exp(raw score), log2e pre-folded into q
    }

    float sum = 0.f;
    #pragma unroll
    for (int k = 0; k < 9; k++) sum += score[k];
    const float hwv = __fdividef(__ldg(HW + h), sum);

    float outp[PP];
    #pragma unroll
    for (int pos = 0; pos < PP; pos++) outp[pos] = 0.f;
    #pragma unroll
    for (int k9 = 0; k9 < 9; k9++) {
        const float* vt = st + ((wl4 + k9/3)*6 + (wlm + k9%3))*TSTR + hc*HSTR + 2*SEC;
        float vv[SEC];
        #pragma unroll
        for (int s4 = 0; s4 < SEC/4; s4++)
            *(float4*)&vv[s4*4] = *(const float4*)&vt[s4*4];
        #pragma unroll
        for (int pos = 0; pos < PP; pos++) outp[pos] += score[k9] * vv[pos];
    }
    #pragma unroll
    for (int pos = 0; pos < PP; pos++) outp[pos] *= hwv;

    // head reduction over NH adjacent lanes (aligned groups)
    #pragma unroll
    for (int pos = 0; pos < PP; pos++) {
        outp[pos] += __shfl_xor_sync(0xffffffffu, outp[pos], 1);
        if (NH == 4) outp[pos] += __shfl_xor_sync(0xffffffffu, outp[pos], 2);
    }

    if (h == 0 && active) {
        #pragma unroll
        for (int pos = 0; pos < PP; pos++) {
            const int y  = wi*P + pos/P - PADH;
            const int x2 = wj*P + pos%P - PADH;
            if (y >= 0 && x2 >= 0)
                Og[(b*3+c)*65536 + y*256 + x2] = outp[pos];
        }
    }
}

// 5x5 conv (9->3 channels) fused with the final elementwise gate
__global__ __launch_bounds__(128) void conv_final_kernel(
    const float* __restrict__ X, const float* __restrict__ CW,
    const float* __restrict__ CB, float* __restrict__ out)
{
    __shared__ float sx[9][20][37];
    __shared__ float sw[675];
    __shared__ float sb[3];
    const int b = blockIdx.z;
    const int x0 = blockIdx.x * 32, y0 = blockIdx.y * 16;
    const int tid = threadIdx.x;

    for (int i2 = tid; i2 < 675; i2 += 128) sw[i2] = CW[i2];
    if (tid < 3) sb[tid] = CB[tid];
    for (int i2 = tid; i2 < 9*20*36; i2 += 128) {
        int ci = i2 / 720, rem = i2 % 720, yy = rem / 36, xx = rem % 36;
        int gy = y0 + yy - 2, gx = x0 + xx - 2;
        float v = 0.f;
        if ((unsigned)gy < 256u && (unsigned)gx < 256u) {
            const float* src = (ci < 3) ? g_x9 : ((ci < 6) ? g_x6 : g_x3);
            v = src[(b*3 + (ci % 3))*65536 + gy*256 + gx];
        }
        sx[ci][yy][xx] = v;
    }
    __syncthreads();

    const int tx = tid & 15, ty = tid >> 4;
    const int lx = tx*2, ly = ty*2;
    float acc[3][4];
    #pragma unroll
    for (int c2 = 0; c2 < 3; c2++)
        #pragma unroll
        for (int p2 = 0; p2 < 4; p2++) acc[c2][p2] = 0.f;

    #pragma unroll 1
    for (int ci = 0; ci < 9; ci++) {
        #pragma unroll
        for (int ky = 0; ky < 5; ky++) {
            #pragma unroll
            for (int kx = 0; kx < 5; kx++) {
                float w0 = sw[      ci*25 + ky*5 + kx];
                float w1 = sw[225 + ci*25 + ky*5 + kx];
                float w2 = sw[450 + ci*25 + ky*5 + kx];
                float a00 = sx[ci][ly+ky  ][lx+kx  ];
                float a01 = sx[ci][ly+ky  ][lx+kx+1];
                float a10 = sx[ci][ly+ky+1][lx+kx  ];
                float a11 = sx[ci][ly+ky+1][lx+kx+1];
                acc[0][0] += w0*a00; acc[0][1] += w0*a01; acc[0][2] += w0*a10; acc[0][3] += w0*a11;
                acc[1][0] += w1*a00; acc[1][1] += w1*a01; acc[1][2] += w1*a10; acc[1][3] += w1*a11;
                acc[2][0] += w2*a00; acc[2][1] += w2*a01; acc[2][2] += w2*a10; acc[2][3] += w2*a11;
            }
        }
    }

    const float xg = g_xg[b];
    #pragma unroll
    for (int co = 0; co < 3; co++) {
        #pragma unroll
        for (int py = 0; py < 2; py++) {
            #pragma unroll
            for (int px = 0; px < 2; px++) {
                int gy = y0 + ly + py, gx = x0 + lx + px;
                float x0v = fmaxf(acc[co][py*2+px] + sb[co], 0.f);
                float xv = X[(b*3+co)*65536 + gy*256 + gx];
                float r = fmaxf(xv * x0v + xg - x0v, 0.f);
                out[(b*3+co)*65536 + gy*256 + gx] = r;
            }
        }
    }
}

extern "C" void kernel_launch(void* const* d_in, const int* in_sizes, int n_in,
                              void* d_out, int out_size) {
    (void)in_sizes; (void)n_in; (void)out_size;
    const float* x   = (const float*)d_in[0];
    const float* w3  = (const float*)d_in[1];
    const float* b3  = (const float*)d_in[2];
    const float* hw3 = (const float*)d_in[3];
    const float* w6  = (const float*)d_in[4];
    const float* b6  = (const float*)d_in[5];
    const float* hw6 = (const float*)d_in[6];
    const float* w9  = (const float*)d_in[7];
    const float* b9  = (const float*)d_in[8];
    const float* hw9 = (const float*)d_in[9];
    const float* cw  = (const float*)d_in[10];
    const float* cb  = (const float*)d_in[11];
    float* out = (float*)d_out;

    // reset g_xg (x >= 0 so zero-init is a valid identity for max)
    void* xg_ptr = nullptr;
    cudaGetSymbolAddress(&xg_ptr, g_xg);
    cudaMemsetAsync(xg_ptr, 0, 4*sizeof(float));

    attn1_kernel<<<8192, 192>>>(x, w3, b3, hw3);

    // stage 2: P=2, NH=4. tiles: 4*130*130 = 67600 -> 2113 blocks of 32 tiles
    proj_kernel<2, 4><<<(67600 + 31) / 32, 12*32>>>(w6, b6);
    attn_win_kernel<2, 4><<<dim3(32, 32, 4), 16*12>>>(hw6);

    // stage 3: P=3, NH=2. tiles: 4*88*88 = 30976 -> 968 blocks of 32 tiles
    proj_kernel<3, 2><<<30976/32, 6*32>>>(w9, b9);
    attn_win_kernel<3, 2><<<dim3(22, 22, 4), 16*6>>>(hw9);

    conv_final_kernel<<<dim3(8, 16, 4), 128>>>(x, cw, cb, out);
}